// round 16
// baseline (speedup 1.0000x reference)
#include <cuda_runtime.h>
#include <cuda_bf16.h>
#include <math.h>
#include <stdint.h>

// Problem constants
#define B_SZ   128
#define T_SEQ  256
#define EMB    384
#define NH     6
#define HD     64
#define WIN    64
#define M_ROWS (B_SZ * T_SEQ)        // 32768
#define QKV_N  (3 * EMB)             // 1152

// Scratch (no cudaMalloc allowed) — device globals.
__device__ float g_qkv[(size_t)M_ROWS * QKV_N];  // [M, 1152]
__device__ float g_y[(size_t)M_ROWS * EMB];      // [M, 384] tf32, A-permuted
__device__ float g_xr[(size_t)M_ROWS * EMB];     // tf32, A-permuted x
__device__ float g_war[(size_t)EMB * QKV_N];     // tf32 W_attn, pair-packed
__device__ float g_wpr[(size_t)EMB * EMB];       // tf32 W_proj, pair-packed

// ---------------------------------------------------------------------------
// tf32 + permutation helpers
// ---------------------------------------------------------------------------
__device__ __forceinline__ float to_tf32(float x) {
    uint32_t u;
    asm("cvt.rna.tf32.f32 %0, %1;" : "=r"(u) : "f"(x));
    return __uint_as_float(u);
}
// A-side k-permutation within a 16-block: pairs (k, k+4) adjacent.
__device__ __forceinline__ int permk(int k) {
    return (k & 8) + 2 * (k & 3) + ((k >> 2) & 1);
}
__device__ __forceinline__ int invp(int p) {
    return (p & 8) | ((p >> 1) & 3) | ((p & 1) << 2);
}

__device__ __forceinline__ void mma_tf32(float c[4],
    uint32_t a0, uint32_t a1, uint32_t a2, uint32_t a3,
    uint32_t b0, uint32_t b1)
{
    asm volatile(
        "mma.sync.aligned.m16n8k8.row.col.f32.tf32.tf32.f32 "
        "{%0,%1,%2,%3}, {%4,%5,%6,%7}, {%8,%9}, {%0,%1,%2,%3};"
        : "+f"(c[0]), "+f"(c[1]), "+f"(c[2]), "+f"(c[3])
        : "r"(a0), "r"(a1), "r"(a2), "r"(a3), "r"(b0), "r"(b1));
}

__device__ __forceinline__ void cp_async16(uint32_t saddr, const float* g) {
    asm volatile("cp.async.cg.shared.global [%0], [%1], 16;" :: "r"(saddr), "l"(g));
}
#define CP_COMMIT() asm volatile("cp.async.commit_group;" ::: "memory")
#define CP_WAIT(n)  asm volatile("cp.async.wait_group %0;" :: "n"(n) : "memory")

// ---------------------------------------------------------------------------
// Pre-transform kernels
// ---------------------------------------------------------------------------
__global__ void round_tf32_perm_kernel(const float* __restrict__ in,
                                       float* __restrict__ out, int n4)
{
    for (int i = blockIdx.x * blockDim.x + threadIdx.x; i < n4;
         i += gridDim.x * blockDim.x) {
        const int blk = (i >> 2) << 4;
        const int p0  = (i & 3) * 4;
        float4 v;
        v.x = to_tf32(in[blk + invp(p0 + 0)]);
        v.y = to_tf32(in[blk + invp(p0 + 1)]);
        v.z = to_tf32(in[blk + invp(p0 + 2)]);
        v.w = to_tf32(in[blk + invp(p0 + 3)]);
        ((float4*)out)[i] = v;
    }
}

// B operand (weights): pack W[384][N] into Wp[[kb][r][n][p]]:
//   k = kb*16 + (r>>2)*8 + (r&3) + 4*p,  addr = (kb*8+r)*(2N) + 2n + p.
__global__ void pack_w_kernel(const float* __restrict__ in,
                              float* __restrict__ out, int N, int n4)
{
    for (int i = blockIdx.x * blockDim.x + threadIdx.x; i < n4;
         i += gridDim.x * blockDim.x) {
        const int pos = i * 4;
        const int row = pos / (2 * N);      // kb*8 + r
        const int rem = pos % (2 * N);
        const int n0  = rem >> 1;
        const int kb  = row >> 3, r = row & 7;
        const int k0  = kb * 16 + (r >> 2) * 8 + (r & 3);
        const int k1  = k0 + 4;
        float4 v;
        v.x = to_tf32(in[(size_t)k0 * N + n0]);
        v.y = to_tf32(in[(size_t)k1 * N + n0]);
        v.z = to_tf32(in[(size_t)k0 * N + n0 + 1]);
        v.w = to_tf32(in[(size_t)k1 * N + n0 + 1]);
        ((float4*)out)[i] = v;
    }
}

// ---------------------------------------------------------------------------
// tf32 tensor-core GEMM, 3-stage cp.async pipeline, 3 CTAs/SM (24 warps).
// C[M,N] = A[M,384] @ B[384,N] + bias[N]
// A stored k-permuted; B stored pair-packed.
// BM=128, BN=128, BK=16, 256 threads (8 warps 2x4), warp tile 64x32.
// A smem [m][k'] stride 24; B smem [8 rows][128 n][2] row stride 264.
// Fragments loaded per k8-half (sequential) to fit the 85-reg budget.
// ---------------------------------------------------------------------------
#define GBM 128
#define GBN 128
#define GBK 16
#define AS_ST 24
#define BS_ST 264
#define NKT (EMB / GBK)          // 24
#define STAGES 3
#define AS_STAGE (GBM * AS_ST)   // 3072 floats
#define BS_STAGE (8 * BS_ST)     // 2112 floats
#define GEMM_SMEM_F (STAGES * (AS_STAGE + BS_STAGE))   // 15552 floats = 62208 B

__global__ __launch_bounds__(256, 3) void gemm_tf32_kernel(
    const float* __restrict__ A, const float* __restrict__ Bm,
    const float* __restrict__ bias, float* __restrict__ C, int N)
{
    extern __shared__ float smem[];
    float* As = smem;                          // [STAGES][GBM][AS_ST]
    float* Bs = smem + STAGES * AS_STAGE;      // [STAGES][8][BS_ST]
    const uint32_t smem_base = (uint32_t)__cvta_generic_to_shared(smem);
    const uint32_t bs_base   = smem_base + STAGES * AS_STAGE * 4u;

    const int tid  = threadIdx.x;
    const int lane = tid & 31;
    const int wid  = tid >> 5;
    const int warp_m = wid >> 2;   // 0..1
    const int warp_n = wid & 3;    // 0..3
    const int m0 = blockIdx.y * GBM;
    const int n0 = blockIdx.x * GBN;

    // A loader: rows ar, ar+64; 16B chunk ak
    const int ar = tid >> 2;
    const int ak = (tid & 3) * 4;
    // B loader: row br (0..7), chunks bc, bc+32
    const int br = tid >> 5;
    const int bc = tid & 31;

    const float* Ag = A + (size_t)m0 * EMB;
    const float* Bg = Bm + (size_t)n0 * 2;   // packed: 2 floats per n

    const uint32_t a_off0 = (uint32_t)((ar * AS_ST + ak) * 4);
    const uint32_t a_off1 = (uint32_t)(((ar + 64) * AS_ST + ak) * 4);
    const uint32_t b_off0 = (uint32_t)((br * BS_ST + bc * 4) * 4);
    const uint32_t b_off1 = (uint32_t)((br * BS_ST + bc * 4 + 128) * 4);

    auto issue_stage = [&](int kt, int s) {
        const int k0 = kt * GBK;
        const uint32_t as_s = smem_base + (uint32_t)(s * AS_STAGE * 4);
        const uint32_t bs_s = bs_base   + (uint32_t)(s * BS_STAGE * 4);
        cp_async16(as_s + a_off0, Ag + (size_t)ar * EMB + k0 + ak);
        cp_async16(as_s + a_off1, Ag + (size_t)(ar + 64) * EMB + k0 + ak);
        const float* brow = Bg + (size_t)(kt * 8 + br) * (2 * N);
        cp_async16(bs_s + b_off0, brow + bc * 4);
        cp_async16(bs_s + b_off1, brow + bc * 4 + 128);
        CP_COMMIT();
    };

    float c[4][4][4];
    #pragma unroll
    for (int mt = 0; mt < 4; mt++)
        #pragma unroll
        for (int nt = 0; nt < 4; nt++)
            #pragma unroll
            for (int i = 0; i < 4; i++) c[mt][nt][i] = 0.f;

    #pragma unroll
    for (int s = 0; s < STAGES - 1; s++) issue_stage(s, s);

    const int lg = lane >> 2;
    const int lt = lane & 3;

    #pragma unroll 1
    for (int kt = 0; kt < NKT; kt++) {
        CP_WAIT(STAGES - 2);
        __syncthreads();

        const int nk = kt + STAGES - 1;
        if (nk < NKT) issue_stage(nk, nk % STAGES);
        else          CP_COMMIT();   // keep group arithmetic exact in tail

        const int s = kt % STAGES;
        const float* as = As + s * AS_STAGE;
        const float* bs = Bs + s * BS_STAGE;

        // Sequential halves: load frags for h, run MMAs for h.
        #pragma unroll
        for (int h = 0; h < 2; h++) {
            float2 bfr[4];
            float2 afr[4][2];
            #pragma unroll
            for (int nt = 0; nt < 4; nt++) {
                const int nb2 = (warp_n * 32 + nt * 8 + lg) * 2;
                bfr[nt] = *(const float2*)&bs[(h * 4 + lt) * BS_ST + nb2];
            }
            #pragma unroll
            for (int mt = 0; mt < 4; mt++) {
                const int mb = warp_m * 64 + mt * 16 + lg;
                afr[mt][0] = *(const float2*)&as[mb * AS_ST + h * 8 + 2 * lt];
                afr[mt][1] = *(const float2*)&as[(mb + 8) * AS_ST + h * 8 + 2 * lt];
            }
            #pragma unroll
            for (int mt = 0; mt < 4; mt++) {
                const uint32_t a0 = __float_as_uint(afr[mt][0].x);
                const uint32_t a2 = __float_as_uint(afr[mt][0].y);
                const uint32_t a1 = __float_as_uint(afr[mt][1].x);
                const uint32_t a3 = __float_as_uint(afr[mt][1].y);
                #pragma unroll
                for (int nt = 0; nt < 4; nt++)
                    mma_tf32(c[mt][nt], a0, a1, a2, a3,
                             __float_as_uint(bfr[nt].x),
                             __float_as_uint(bfr[nt].y));
            }
        }
    }

    // epilogue: add bias, store (canonical layout)
    #pragma unroll
    for (int mt = 0; mt < 4; mt++) {
        const int row = m0 + warp_m * 64 + mt * 16 + lg;
        #pragma unroll
        for (int nt = 0; nt < 4; nt++) {
            const int col = n0 + warp_n * 32 + nt * 8 + lt * 2;
            const float b0 = bias[col], b1 = bias[col + 1];
            float2 v0 = make_float2(c[mt][nt][0] + b0, c[mt][nt][1] + b1);
            float2 v1 = make_float2(c[mt][nt][2] + b0, c[mt][nt][3] + b1);
            *(float2*)&C[(size_t)row * N + col]       = v0;
            *(float2*)&C[(size_t)(row + 8) * N + col] = v1;
        }
    }
}

// ---------------------------------------------------------------------------
// Banded causal attention — tensor cores, band skipping (unchanged r15).
// Q/K stored with d-dimension pair-permuted (stride 72) -> LDS.64 fragments.
// V stored row-major [s][d] stride 72 -> direct col-major B reads.
// Epilogue writes g_y tf32-rounded AND A-permuted (GEMM2's A operand).
// ---------------------------------------------------------------------------
#define QT 64
#define KT 128
#define QK_ST 72
#define VS_ST 72
#define SS_ST 136

#define SM_V    0
#define SM_Q    (KT * VS_ST)             // 9216
#define SM_K    (SM_Q + QT * QK_ST)      // 13824
#define SM_S    SM_Q                     // S aliases Q+K after phase 1
#define SM_TOTF (SM_K + KT * QK_ST)      // 23040 floats = 92160 B

__global__ __launch_bounds__(256, 2) void attn_kernel(
    const float* __restrict__ qkv, float* __restrict__ y)
{
    extern __shared__ float sm[];
    float* Vs = sm + SM_V;
    float* Qs = sm + SM_Q;
    float* Ks = sm + SM_K;
    float* Ss = sm + SM_S;

    const int q0  = blockIdx.x * QT;
    const int h   = blockIdx.y;
    const int b   = blockIdx.z;
    const int tid = threadIdx.x;
    const int hoff = h * HD;

    const float* base = qkv + (size_t)b * T_SEQ * QKV_N;

    for (int idx = tid; idx < KT * 8; idx += 256) {
        const int s = idx >> 3, g = idx & 7;
        const int j = q0 - WIN + s;
        float4 c0, c1;
        if (j >= 0 && j < T_SEQ) {
            const float* row = base + (size_t)j * QKV_N + EMB + hoff + g * 8;
            c0 = *(const float4*)(row);
            c1 = *(const float4*)(row + 4);
        } else {
            c0 = make_float4(0.f, 0.f, 0.f, 0.f);
            c1 = c0;
        }
        float4 o0 = make_float4(to_tf32(c0.x), to_tf32(c1.x), to_tf32(c0.y), to_tf32(c1.y));
        float4 o1 = make_float4(to_tf32(c0.z), to_tf32(c1.z), to_tf32(c0.w), to_tf32(c1.w));
        *(float4*)(Ks + s * QK_ST + g * 8)     = o0;
        *(float4*)(Ks + s * QK_ST + g * 8 + 4) = o1;
    }
    for (int idx = tid; idx < QT * 8; idx += 256) {
        const int qi = idx >> 3, g = idx & 7;
        const float* row = base + (size_t)(q0 + qi) * QKV_N + hoff + g * 8;
        float4 c0 = *(const float4*)(row);
        float4 c1 = *(const float4*)(row + 4);
        float4 o0 = make_float4(to_tf32(c0.x), to_tf32(c1.x), to_tf32(c0.y), to_tf32(c1.y));
        float4 o1 = make_float4(to_tf32(c0.z), to_tf32(c1.z), to_tf32(c0.w), to_tf32(c1.w));
        *(float4*)(Qs + qi * QK_ST + g * 8)     = o0;
        *(float4*)(Qs + qi * QK_ST + g * 8 + 4) = o1;
    }
    for (int idx = tid; idx < KT * 16; idx += 256) {
        const int s = idx >> 4, f = idx & 15;
        const int j = q0 - WIN + s;
        float4 vv;
        if (j >= 0 && j < T_SEQ) {
            vv = *(const float4*)(base + (size_t)j * QKV_N + 2 * EMB + hoff + f * 4);
        } else {
            vv = make_float4(0.f, 0.f, 0.f, 0.f);
        }
        float4 t;
        t.x = to_tf32(vv.x); t.y = to_tf32(vv.y); t.z = to_tf32(vv.z); t.w = to_tf32(vv.w);
        *(float4*)(Vs + s * VS_ST + f * 4) = t;
    }
    __syncthreads();

    const int lane = tid & 31;
    const int wid  = tid >> 5;
    const int lg = lane >> 2;
    const int lt = lane & 3;
    const int mt = wid & 3;
    const int nh = wid >> 2;
    const int mrow = mt * 16 + lg;

    const int lo = max(mt * 16, WIN - q0);
    const int hi = mt * 16 + 15 + WIN;

    float sc[8][4];
    #pragma unroll
    for (int nt = 0; nt < 8; nt++)
        #pragma unroll
        for (int i = 0; i < 4; i++) sc[nt][i] = 0.f;

    bool ntv[8];
    #pragma unroll
    for (int nt = 0; nt < 8; nt++) {
        const int cb = nh * 64 + nt * 8;
        ntv[nt] = (cb + 7 >= lo) && (cb <= hi);
    }

    #pragma unroll
    for (int k0 = 0; k0 < HD; k0 += 8) {
        float2 aq0 = *(const float2*)&Qs[mrow * QK_ST + k0 + 2 * lt];
        float2 aq1 = *(const float2*)&Qs[(mrow + 8) * QK_ST + k0 + 2 * lt];
        const uint32_t a0 = __float_as_uint(aq0.x);
        const uint32_t a2 = __float_as_uint(aq0.y);
        const uint32_t a1 = __float_as_uint(aq1.x);
        const uint32_t a3 = __float_as_uint(aq1.y);
        #pragma unroll
        for (int nt = 0; nt < 8; nt++) {
            if (!ntv[nt]) continue;
            const int nb = nh * 64 + nt * 8 + lg;
            float2 bk = *(const float2*)&Ks[nb * QK_ST + k0 + 2 * lt];
            mma_tf32(sc[nt], a0, a1, a2, a3,
                     __float_as_uint(bk.x), __float_as_uint(bk.y));
        }
    }
    __syncthreads();

    #pragma unroll
    for (int nt = 0; nt < 8; nt++) {
        const int col = nh * 64 + nt * 8 + lt * 2;
        *(float2*)(Ss + mrow * SS_ST + col)       = make_float2(sc[nt][0], sc[nt][1]);
        *(float2*)(Ss + (mrow + 8) * SS_ST + col) = make_float2(sc[nt][2], sc[nt][3]);
    }
    __syncthreads();

    {
        const int qi = tid >> 2;
        const int kg = tid & 3;
        const int smin = max(qi, WIN - q0);
        const int smax = qi + WIN;
        float* srow = Ss + qi * SS_ST;

        float v[32];
        float m = -1e30f;
        #pragma unroll
        for (int si = 0; si < 32; si++) {
            const int s = si * 4 + kg;
            const bool ok = (s >= smin) && (s <= smax);
            float t = ok ? srow[s] * 0.125f : -1e30f;
            v[si] = t;
            m = fmaxf(m, t);
        }
        m = fmaxf(m, __shfl_xor_sync(0xffffffffu, m, 1));
        m = fmaxf(m, __shfl_xor_sync(0xffffffffu, m, 2));
        float ssum = 0.f;
        #pragma unroll
        for (int si = 0; si < 32; si++) {
            float e = __expf(v[si] - m);
            v[si] = e;
            ssum += e;
        }
        ssum += __shfl_xor_sync(0xffffffffu, ssum, 1);
        ssum += __shfl_xor_sync(0xffffffffu, ssum, 2);
        const float inv = 1.f / ssum;
        #pragma unroll
        for (int si = 0; si < 32; si++)
            srow[si * 4 + kg] = to_tf32(v[si] * inv);
    }
    __syncthreads();

    float oc[4][4];
    #pragma unroll
    for (int nt = 0; nt < 4; nt++)
        #pragma unroll
        for (int i = 0; i < 4; i++) oc[nt][i] = 0.f;

    #pragma unroll
    for (int k0 = 0; k0 < KT; k0 += 8) {
        if (k0 + 7 < lo || k0 > hi) continue;
        uint32_t a0 = __float_as_uint(Ss[mrow * SS_ST + k0 + lt]);
        uint32_t a1 = __float_as_uint(Ss[(mrow + 8) * SS_ST + k0 + lt]);
        uint32_t a2 = __float_as_uint(Ss[mrow * SS_ST + k0 + 4 + lt]);
        uint32_t a3 = __float_as_uint(Ss[(mrow + 8) * SS_ST + k0 + 4 + lt]);
        #pragma unroll
        for (int nt = 0; nt < 4; nt++) {
            const int nb = nh * 32 + nt * 8 + lg;
            uint32_t b0 = __float_as_uint(Vs[(k0 + lt) * VS_ST + nb]);
            uint32_t b1 = __float_as_uint(Vs[(k0 + 4 + lt) * VS_ST + nb]);
            mma_tf32(oc[nt], a0, a1, a2, a3, b0, b1);
        }
    }

    {
        const int row0 = b * T_SEQ + q0 + mrow;
        #pragma unroll
        for (int nt = 0; nt < 4; nt++) {
            const int c = hoff + nh * 32 + nt * 8 + lt * 2;
            const int blk = c & ~15;
            const int o0 = permk(c & 15);
            const int o1 = permk((c & 15) + 1);
            y[(size_t)row0 * EMB + blk + o0]       = to_tf32(oc[nt][0]);
            y[(size_t)row0 * EMB + blk + o1]       = to_tf32(oc[nt][1]);
            y[(size_t)(row0 + 8) * EMB + blk + o0] = to_tf32(oc[nt][2]);
            y[(size_t)(row0 + 8) * EMB + blk + o1] = to_tf32(oc[nt][3]);
        }
    }
}

// ---------------------------------------------------------------------------
// Launch
// ---------------------------------------------------------------------------
extern "C" void kernel_launch(void* const* d_in, const int* in_sizes, int n_in,
                              void* d_out, int out_size)
{
    const float* x      = (const float*)d_in[0];  // [128,256,384]
    const float* W_attn = (const float*)d_in[1];  // [384,1152]
    const float* b_attn = (const float*)d_in[2];  // [1152]
    const float* W_proj = (const float*)d_in[3];  // [384,384]
    const float* b_proj = (const float*)d_in[4];  // [384]
    float* out = (float*)d_out;                   // [128,256,384]

    float *qkv_ptr = nullptr, *y_ptr = nullptr;
    float *xr_ptr = nullptr, *war_ptr = nullptr, *wpr_ptr = nullptr;
    cudaGetSymbolAddress((void**)&qkv_ptr, g_qkv);
    cudaGetSymbolAddress((void**)&y_ptr, g_y);
    cudaGetSymbolAddress((void**)&xr_ptr, g_xr);
    cudaGetSymbolAddress((void**)&war_ptr, g_war);
    cudaGetSymbolAddress((void**)&wpr_ptr, g_wpr);

    // 0) pre-transform GEMM inputs (A permuted; B pair-packed)
    {
        const int nx = M_ROWS * EMB / 4;
        round_tf32_perm_kernel<<<2048, 256>>>(x, xr_ptr, nx);
        const int na = EMB * QKV_N / 4;
        pack_w_kernel<<<432, 256>>>(W_attn, war_ptr, QKV_N, na);
        const int np = EMB * EMB / 4;
        pack_w_kernel<<<144, 256>>>(W_proj, wpr_ptr, EMB, np);
    }

    const int gemm_smem = GEMM_SMEM_F * (int)sizeof(float);   // 62208 B
    cudaFuncSetAttribute(gemm_tf32_kernel, cudaFuncAttributeMaxDynamicSharedMemorySize, gemm_smem);

    // 1) qkv = xr @ W_attn_packed + b_attn
    {
        dim3 grid(QKV_N / GBN, M_ROWS / GBM);
        gemm_tf32_kernel<<<grid, 256, gemm_smem>>>(xr_ptr, war_ptr, b_attn, qkv_ptr, QKV_N);
    }

    // 2) banded attention (tensor cores) -> g_y (tf32, A-permuted)
    {
        const int smem_bytes = SM_TOTF * (int)sizeof(float);   // 92160 B
        cudaFuncSetAttribute(attn_kernel, cudaFuncAttributeMaxDynamicSharedMemorySize, smem_bytes);
        dim3 grid(T_SEQ / QT, NH, B_SZ);
        attn_kernel<<<grid, 256, smem_bytes>>>(qkv_ptr, y_ptr);
    }

    // 3) out = y @ W_proj_packed + b_proj
    {
        dim3 grid(EMB / GBN, M_ROWS / GBM);
        gemm_tf32_kernel<<<grid, 256, gemm_smem>>>(y_ptr, wpr_ptr, b_proj, out, EMB);
    }
}